// round 1
// baseline (speedup 1.0000x reference)
#include <cuda_runtime.h>
#include <math.h>
#include <stdint.h>

// Problem: out[b,k,j,c] = (log(|y|+1e-13) - mean[k,j,c]) / std[k,j,c]
//   y[b,k,j,c] = sum_w ( sum_h D[k,h] x[b,h,w,c] ) * D[j,w]
// D built EXACTLY like the jax reference (fp32 argument rounding included).

#define NB   128
#define NN   256
#define NC   3
#define NPLANES (NB*NC)   // 384

__device__ float g_D[NN * NN];
__device__ float g_S1[(size_t)NPLANES * NN * NN];   // T[p][k][w], ~100 MB

// ---------------------------------------------------------------------------
// Build D replicating jax fp32 op order:
//   arg = ((float(pi) * (h+0.5f)) * float(k)) / 256.0f      (all fp32 rounds)
//   D   = cos(arg) * float(sqrt(2/256));  row 0 *= float(1/float(sqrt(2)))
// cos evaluated in double of the fp32 arg (>= accuracy of XLA's f32 cos).
// ---------------------------------------------------------------------------
__global__ void compute_D_kernel() {
    int k = blockIdx.x;
    int h = threadIdx.x;
    float a = 3.14159274101257324f * ((float)h + 0.5f);
    a = a * (float)k;
    a = a * 0.00390625f;            // /256.0f, exact power of two
    float v = (float)cos((double)a);
    v = v * 0.088388347f;           // fp32(sqrt(2/256))
    if (k == 0) v = v * 0.70710677f; // fp32(1/fp32(sqrt(2)))
    g_D[k * NN + h] = v;
}

// ---------------------------------------------------------------------------
// ~1-ulp fp32 log, FMA-only (immune to --use_fast_math logf degradation).
// Input guaranteed > 0 and >= 1e-13 (normal).
// ---------------------------------------------------------------------------
__device__ __forceinline__ float log_precise(float x) {
    unsigned ix = __float_as_uint(x);
    int e = (int)(ix >> 23) - 126;                       // m in [0.5, 1)
    float m = __uint_as_float((ix & 0x007FFFFFu) | 0x3F000000u);
    if (m < 0.70710678f) { m = m + m; e -= 1; }          // m in [~0.7071, 1.4142)
    float f = m - 1.0f;
    float z = f * f;
    float p =            7.0376836292e-2f;
    p = fmaf(p, f, -1.1514610310e-1f);
    p = fmaf(p, f,  1.1676998740e-1f);
    p = fmaf(p, f, -1.2420140846e-1f);
    p = fmaf(p, f,  1.4249322787e-1f);
    p = fmaf(p, f, -1.6668057665e-1f);
    p = fmaf(p, f,  2.0000714765e-1f);
    p = fmaf(p, f, -2.4999993993e-1f);
    p = fmaf(p, f,  3.3333331174e-1f);
    float y = f * z * p;
    float fe = (float)e;
    y = fmaf(fe, -2.12194440e-4f, y);   // ln2_lo
    y = fmaf(-0.5f, z, y);
    float r = f + y;
    r = fmaf(fe, 0.693359375f, r);      // ln2_hi
    return r;
}

// ---------------------------------------------------------------------------
// GEMM1: T[p][k][w] = sum_h D[k,h] * x[b,h,w,c],  p = b*3+c
// grid (4, 384): blockIdx.x -> 2x2 tiles of the 256x256 output, 128x128/CTA.
// 256 threads, 8x8 microtile, k-tile (over h) = 16.
// ---------------------------------------------------------------------------
__global__ void __launch_bounds__(256, 2) dct_gemm1(const float* __restrict__ x) {
    __shared__ float As[16][132];   // As[hh][kk] = D[tk+kk][h0+hh]
    __shared__ float Bs[16][132];   // Bs[hh][ww] = x[b][h0+hh][tw+ww][c]

    int p  = blockIdx.y;
    int b  = p / 3;
    int c  = p - 3 * b;
    int tk = (blockIdx.x >> 1) << 7;
    int tw = (blockIdx.x & 1) << 7;
    int tid = threadIdx.x;
    int tx = tid & 15, ty = tid >> 4;

    const float* xb = x + (size_t)b * (NN * NN * NC) + c;

    float acc[8][8];
    #pragma unroll
    for (int i = 0; i < 8; i++)
        #pragma unroll
        for (int j = 0; j < 8; j++) acc[i][j] = 0.0f;

    for (int h0 = 0; h0 < NN; h0 += 16) {
        #pragma unroll
        for (int l = 0; l < 8; l++) {
            int idx = tid + l * 256;
            int kk = idx >> 4, hh = idx & 15;
            As[hh][kk] = g_D[(tk + kk) * NN + h0 + hh];
        }
        #pragma unroll
        for (int l = 0; l < 8; l++) {
            int idx = tid + l * 256;
            int hh = idx >> 7, ww = idx & 127;
            Bs[hh][ww] = xb[(size_t)(h0 + hh) * (NN * NC) + (size_t)(tw + ww) * NC];
        }
        __syncthreads();

        #pragma unroll
        for (int hh = 0; hh < 16; hh++) {
            float a[8], bb[8];
            #pragma unroll
            for (int i = 0; i < 8; i++) a[i]  = As[hh][ty * 8 + i];
            #pragma unroll
            for (int j = 0; j < 8; j++) bb[j] = Bs[hh][tx * 8 + j];
            #pragma unroll
            for (int i = 0; i < 8; i++)
                #pragma unroll
                for (int j = 0; j < 8; j++)
                    acc[i][j] = fmaf(a[i], bb[j], acc[i][j]);
        }
        __syncthreads();
    }

    float* S = g_S1 + (size_t)p * (NN * NN);
    #pragma unroll
    for (int i = 0; i < 8; i++) {
        int row = tk + ty * 8 + i;
        #pragma unroll
        for (int j = 0; j < 8; j++)
            S[row * NN + tw + tx * 8 + j] = acc[i][j];
    }
}

// ---------------------------------------------------------------------------
// GEMM2: U[k][j] = sum_w T[p][k][w] * D[j][w], then fused log/normalize,
// scatter to out[b][k][j][c].
// ---------------------------------------------------------------------------
__global__ void __launch_bounds__(256, 2) dct_gemm2(const float* __restrict__ mean,
                                                    const float* __restrict__ stdv,
                                                    float* __restrict__ out) {
    __shared__ float As[16][132];   // As[ww][kk] = T[tk+kk][w0+ww]
    __shared__ float Bs[16][132];   // Bs[ww][jj] = D[tj+jj][w0+ww]

    int p  = blockIdx.y;
    int b  = p / 3;
    int c  = p - 3 * b;
    int tk = (blockIdx.x >> 1) << 7;
    int tj = (blockIdx.x & 1) << 7;
    int tid = threadIdx.x;
    int tx = tid & 15, ty = tid >> 4;

    const float* T = g_S1 + (size_t)p * (NN * NN);

    float acc[8][8];
    #pragma unroll
    for (int i = 0; i < 8; i++)
        #pragma unroll
        for (int j = 0; j < 8; j++) acc[i][j] = 0.0f;

    for (int w0 = 0; w0 < NN; w0 += 16) {
        #pragma unroll
        for (int l = 0; l < 8; l++) {
            int idx = tid + l * 256;
            int kk = idx >> 4, ww = idx & 15;
            As[ww][kk] = T[(tk + kk) * NN + w0 + ww];
        }
        #pragma unroll
        for (int l = 0; l < 8; l++) {
            int idx = tid + l * 256;
            int jj = idx >> 4, ww = idx & 15;
            Bs[ww][jj] = g_D[(tj + jj) * NN + w0 + ww];
        }
        __syncthreads();

        #pragma unroll
        for (int ww = 0; ww < 16; ww++) {
            float a[8], bb[8];
            #pragma unroll
            for (int i = 0; i < 8; i++) a[i]  = As[ww][ty * 8 + i];
            #pragma unroll
            for (int j = 0; j < 8; j++) bb[j] = Bs[ww][tx * 8 + j];
            #pragma unroll
            for (int i = 0; i < 8; i++)
                #pragma unroll
                for (int j = 0; j < 8; j++)
                    acc[i][j] = fmaf(a[i], bb[j], acc[i][j]);
        }
        __syncthreads();
    }

    #pragma unroll
    for (int i = 0; i < 8; i++) {
        int k = tk + ty * 8 + i;
        #pragma unroll
        for (int j = 0; j < 8; j++) {
            int jj = tj + tx * 8 + j;
            float y = acc[i][j];
            float z = log_precise(fabsf(y) + 1e-13f);
            int mi = (k * NN + jj) * NC + c;
            float o = (z - mean[mi]) / stdv[mi];
            out[((size_t)(b * NN + k) * NN + jj) * NC + c] = o;
        }
    }
}

// ---------------------------------------------------------------------------
extern "C" void kernel_launch(void* const* d_in, const int* in_sizes, int n_in,
                              void* d_out, int out_size) {
    const float* x    = (const float*)d_in[0];
    const float* mean = (const float*)d_in[1];
    const float* stdv = (const float*)d_in[2];
    float* out = (float*)d_out;

    compute_D_kernel<<<256, 256>>>();
    dct_gemm1<<<dim3(4, NPLANES), 256>>>(x);
    dct_gemm2<<<dim3(4, NPLANES), 256>>>(mean, stdv, out);
}

// round 2
// speedup vs baseline: 1.1194x; 1.1194x over previous
#include <cuda_runtime.h>
#include <math.h>
#include <stdint.h>

#define NB   128
#define NN   256
#define NC   3
#define NPLANES (NB*NC)   // 384

__device__ float g_D[NN * NN];
__device__ float g_S1[(size_t)NPLANES * NN * NN];   // T[p][k][w], ~100 MB

// ---------------------------------------------------------------------------
// Build D replicating jax fp32 op order.
// ---------------------------------------------------------------------------
__global__ void compute_D_kernel() {
    int k = blockIdx.x;
    int h = threadIdx.x;
    float a = 3.14159274101257324f * ((float)h + 0.5f);
    a = a * (float)k;
    a = a * 0.00390625f;            // /256.0f exact
    float v = (float)cos((double)a);
    v = v * 0.088388347f;           // fp32(sqrt(2/256))
    if (k == 0) v = v * 0.70710677f;
    g_D[k * NN + h] = v;
}

// ---------------------------------------------------------------------------
// ~1-ulp fp32 log (immune to --use_fast_math).
// ---------------------------------------------------------------------------
__device__ __forceinline__ float log_precise(float x) {
    unsigned ix = __float_as_uint(x);
    int e = (int)(ix >> 23) - 126;
    float m = __uint_as_float((ix & 0x007FFFFFu) | 0x3F000000u);
    if (m < 0.70710678f) { m = m + m; e -= 1; }
    float f = m - 1.0f;
    float z = f * f;
    float p =            7.0376836292e-2f;
    p = fmaf(p, f, -1.1514610310e-1f);
    p = fmaf(p, f,  1.1676998740e-1f);
    p = fmaf(p, f, -1.2420140846e-1f);
    p = fmaf(p, f,  1.4249322787e-1f);
    p = fmaf(p, f, -1.6668057665e-1f);
    p = fmaf(p, f,  2.0000714765e-1f);
    p = fmaf(p, f, -2.4999993993e-1f);
    p = fmaf(p, f,  3.3333331174e-1f);
    float y = f * z * p;
    float fe = (float)e;
    y = fmaf(fe, -2.12194440e-4f, y);
    y = fmaf(-0.5f, z, y);
    float r = f + y;
    r = fmaf(fe, 0.693359375f, r);
    return r;
}

// ---------------------------------------------------------------------------
// Packed f32x2 helpers (FFMA2 path — 2x fp32 FMA width, rn rounding, bitwise
// identical to two scalar fmaf).
// ---------------------------------------------------------------------------
__device__ __forceinline__ void fma2(unsigned long long& d,
                                     unsigned long long a,
                                     unsigned long long b) {
    asm("fma.rn.f32x2 %0, %1, %2, %3;" : "=l"(d) : "l"(a), "l"(b), "l"(d));
}
__device__ __forceinline__ unsigned long long pack2(float v) {
    unsigned long long r;
    asm("mov.b64 %0, {%1, %1};" : "=l"(r) : "f"(v));
    return r;
}
__device__ __forceinline__ float2 unpack2(unsigned long long v) {
    float2 r;
    asm("mov.b64 {%0, %1}, %2;" : "=f"(r.x), "=f"(r.y) : "l"(v));
    return r;
}

// ---------------------------------------------------------------------------
// GEMM1: T[p][k][w] = sum_h D[k,h] * x[b,h,w,c]
// 128x128 tile / CTA, 256 threads, 8x8 microtile, k-tile 16, double-buffered.
// ---------------------------------------------------------------------------
__global__ void __launch_bounds__(256, 2) dct_gemm1(const float* __restrict__ x) {
    __shared__ float As[2][16][132];   // As[buf][hh][kk] = D[tk+kk][h0+hh]
    __shared__ float Bs[2][16][132];   // Bs[buf][hh][ww] = x[b][h0+hh][tw+ww][c]

    int p  = blockIdx.y;
    int b  = p / 3;
    int c  = p - 3 * b;
    int tk = (blockIdx.x >> 1) << 7;
    int tw = (blockIdx.x & 1) << 7;
    int tid = threadIdx.x;
    int tx = tid & 15, ty = tid >> 4;

    const float* xb = x + (size_t)b * (NN * NN * NC) + c;

    unsigned long long acc[8][4];
    #pragma unroll
    for (int i = 0; i < 8; i++)
        #pragma unroll
        for (int j = 0; j < 4; j++) acc[i][j] = 0ull;

    float ra[8], rb[8];

    // prologue: tile 0 -> regs -> buf 0
    #pragma unroll
    for (int l = 0; l < 8; l++) {
        int idx = tid + l * 256;
        int kk = idx >> 4, hh = idx & 15;
        ra[l] = g_D[(tk + kk) * NN + hh];
    }
    #pragma unroll
    for (int l = 0; l < 8; l++) {
        int idx = tid + l * 256;
        int hh = idx >> 7, ww = idx & 127;
        rb[l] = xb[(size_t)hh * (NN * NC) + (size_t)(tw + ww) * NC];
    }
    #pragma unroll
    for (int l = 0; l < 8; l++) {
        int idx = tid + l * 256;
        As[0][idx & 15][idx >> 4] = ra[l];
    }
    #pragma unroll
    for (int l = 0; l < 8; l++) {
        int idx = tid + l * 256;
        Bs[0][idx >> 7][idx & 127] = rb[l];
    }
    __syncthreads();

    #pragma unroll 1
    for (int t = 0; t < 16; t++) {
        int buf = t & 1;
        int h0n = (t + 1) << 4;
        if (t < 15) {
            #pragma unroll
            for (int l = 0; l < 8; l++) {
                int idx = tid + l * 256;
                int kk = idx >> 4, hh = idx & 15;
                ra[l] = g_D[(tk + kk) * NN + h0n + hh];
            }
            #pragma unroll
            for (int l = 0; l < 8; l++) {
                int idx = tid + l * 256;
                int hh = idx >> 7, ww = idx & 127;
                rb[l] = xb[(size_t)(h0n + hh) * (NN * NC) + (size_t)(tw + ww) * NC];
            }
        }

        #pragma unroll
        for (int hh = 0; hh < 16; hh++) {
            unsigned long long bb[4];
            const unsigned long long* Bp =
                reinterpret_cast<const unsigned long long*>(&Bs[buf][hh][tx * 8]);
            bb[0] = Bp[0]; bb[1] = Bp[1]; bb[2] = Bp[2]; bb[3] = Bp[3];
            const float* Ap = &As[buf][hh][ty * 8];
            #pragma unroll
            for (int i = 0; i < 8; i++) {
                unsigned long long ap = pack2(Ap[i]);
                fma2(acc[i][0], ap, bb[0]);
                fma2(acc[i][1], ap, bb[1]);
                fma2(acc[i][2], ap, bb[2]);
                fma2(acc[i][3], ap, bb[3]);
            }
        }

        if (t < 15) {
            #pragma unroll
            for (int l = 0; l < 8; l++) {
                int idx = tid + l * 256;
                As[buf ^ 1][idx & 15][idx >> 4] = ra[l];
            }
            #pragma unroll
            for (int l = 0; l < 8; l++) {
                int idx = tid + l * 256;
                Bs[buf ^ 1][idx >> 7][idx & 127] = rb[l];
            }
            __syncthreads();
        }
    }

    float* S = g_S1 + (size_t)p * (NN * NN);
    #pragma unroll
    for (int i = 0; i < 8; i++) {
        int row = tk + ty * 8 + i;
        unsigned long long* Sp =
            reinterpret_cast<unsigned long long*>(&S[row * NN + tw + tx * 8]);
        #pragma unroll
        for (int j = 0; j < 4; j++) Sp[j] = acc[i][j];
    }
}

// ---------------------------------------------------------------------------
// GEMM2: U[k][j] = sum_w T[p][k][w] * D[j][w], fused log/normalize epilogue.
// ---------------------------------------------------------------------------
__global__ void __launch_bounds__(256, 2) dct_gemm2(const float* __restrict__ mean,
                                                    const float* __restrict__ stdv,
                                                    float* __restrict__ out) {
    __shared__ float As[2][16][132];   // As[buf][ww][kk] = T[tk+kk][w0+ww]
    __shared__ float Bs[2][16][132];   // Bs[buf][ww][jj] = D[tj+jj][w0+ww]

    int p  = blockIdx.y;
    int b  = p / 3;
    int c  = p - 3 * b;
    int tk = (blockIdx.x >> 1) << 7;
    int tj = (blockIdx.x & 1) << 7;
    int tid = threadIdx.x;
    int tx = tid & 15, ty = tid >> 4;

    const float* T = g_S1 + (size_t)p * (NN * NN);

    unsigned long long acc[8][4];
    #pragma unroll
    for (int i = 0; i < 8; i++)
        #pragma unroll
        for (int j = 0; j < 4; j++) acc[i][j] = 0ull;

    float ra[8], rb[8];

    #pragma unroll
    for (int l = 0; l < 8; l++) {
        int idx = tid + l * 256;
        int kk = idx >> 4, ww = idx & 15;
        ra[l] = T[(tk + kk) * NN + ww];
    }
    #pragma unroll
    for (int l = 0; l < 8; l++) {
        int idx = tid + l * 256;
        int jj = idx >> 4, ww = idx & 15;
        rb[l] = g_D[(tj + jj) * NN + ww];
    }
    #pragma unroll
    for (int l = 0; l < 8; l++) {
        int idx = tid + l * 256;
        As[0][idx & 15][idx >> 4] = ra[l];
    }
    #pragma unroll
    for (int l = 0; l < 8; l++) {
        int idx = tid + l * 256;
        Bs[0][idx & 15][idx >> 4] = rb[l];
    }
    __syncthreads();

    #pragma unroll 1
    for (int t = 0; t < 16; t++) {
        int buf = t & 1;
        int w0n = (t + 1) << 4;
        if (t < 15) {
            #pragma unroll
            for (int l = 0; l < 8; l++) {
                int idx = tid + l * 256;
                int kk = idx >> 4, ww = idx & 15;
                ra[l] = T[(tk + kk) * NN + w0n + ww];
            }
            #pragma unroll
            for (int l = 0; l < 8; l++) {
                int idx = tid + l * 256;
                int jj = idx >> 4, ww = idx & 15;
                rb[l] = g_D[(tj + jj) * NN + w0n + ww];
            }
        }

        #pragma unroll
        for (int ww = 0; ww < 16; ww++) {
            unsigned long long bb[4];
            const unsigned long long* Bp =
                reinterpret_cast<const unsigned long long*>(&Bs[buf][ww][tx * 8]);
            bb[0] = Bp[0]; bb[1] = Bp[1]; bb[2] = Bp[2]; bb[3] = Bp[3];
            const float* Ap = &As[buf][ww][ty * 8];
            #pragma unroll
            for (int i = 0; i < 8; i++) {
                unsigned long long ap = pack2(Ap[i]);
                fma2(acc[i][0], ap, bb[0]);
                fma2(acc[i][1], ap, bb[1]);
                fma2(acc[i][2], ap, bb[2]);
                fma2(acc[i][3], ap, bb[3]);
            }
        }

        if (t < 15) {
            #pragma unroll
            for (int l = 0; l < 8; l++) {
                int idx = tid + l * 256;
                As[buf ^ 1][idx & 15][idx >> 4] = ra[l];
            }
            #pragma unroll
            for (int l = 0; l < 8; l++) {
                int idx = tid + l * 256;
                Bs[buf ^ 1][idx & 15][idx >> 4] = rb[l];
            }
            __syncthreads();
        }
    }

    #pragma unroll
    for (int i = 0; i < 8; i++) {
        int k = tk + ty * 8 + i;
        #pragma unroll
        for (int j = 0; j < 4; j++) {
            float2 v = unpack2(acc[i][j]);
            int jj0 = tj + tx * 8 + 2 * j;
            float z0 = log_precise(fabsf(v.x) + 1e-13f);
            float z1 = log_precise(fabsf(v.y) + 1e-13f);
            int mi0 = (k * NN + jj0) * NC + c;
            int mi1 = mi0 + NC;
            out[((size_t)(b * NN + k) * NN + jj0) * NC + c] = (z0 - mean[mi0]) / stdv[mi0];
            out[((size_t)(b * NN + k) * NN + jj0 + 1) * NC + c] = (z1 - mean[mi1]) / stdv[mi1];
        }
    }
}

// ---------------------------------------------------------------------------
extern "C" void kernel_launch(void* const* d_in, const int* in_sizes, int n_in,
                              void* d_out, int out_size) {
    const float* x    = (const float*)d_in[0];
    const float* mean = (const float*)d_in[1];
    const float* stdv = (const float*)d_in[2];
    float* out = (float*)d_out;

    compute_D_kernel<<<256, 256>>>();
    dct_gemm1<<<dim3(4, NPLANES), 256>>>(x);
    dct_gemm2<<<dim3(4, NPLANES), 256>>>(mean, stdv, out);
}

// round 5
// speedup vs baseline: 1.2949x; 1.1568x over previous
#include <cuda_runtime.h>
#include <cuda_bf16.h>
#include <math.h>
#include <stdint.h>

#define NN 256
#define NC 3
#define NPLANES 384

__device__ float g_S1[(size_t)NPLANES * NN * NN];   // T[p][k][w] fp32
__device__ __nv_bfloat16 g_D0[NN * NN];
__device__ __nv_bfloat16 g_D1[NN * NN];
__device__ __nv_bfloat16 g_D2[NN * NN];

// smem rows: 3 sub-tiles of 16 bf16 (32B each) padded to 112B stride
#define ROWB 112
#define TILEA (128 * ROWB)
#define TILEB_SZ (64 * ROWB)

// ---------------- helpers ----------------
__device__ __forceinline__ uint32_t smem_u32(const void* p) {
    uint32_t a;
    asm("{ .reg .u64 t; cvta.to.shared.u64 t, %1; cvt.u32.u64 %0, t; }" : "=r"(a) : "l"(p));
    return a;
}
__device__ __forceinline__ void ldsm_x4(uint32_t* r, uint32_t addr) {
    asm volatile("ldmatrix.sync.aligned.m8n8.x4.shared.b16 {%0,%1,%2,%3}, [%4];"
        : "=r"(r[0]), "=r"(r[1]), "=r"(r[2]), "=r"(r[3]) : "r"(addr));
}
__device__ __forceinline__ void mma_bf16(float* d, const uint32_t* a, const uint32_t* b) {
    asm volatile("mma.sync.aligned.m16n8k16.row.col.f32.bf16.bf16.f32 "
        "{%0,%1,%2,%3}, {%4,%5,%6,%7}, {%8,%9}, {%0,%1,%2,%3};"
        : "+f"(d[0]), "+f"(d[1]), "+f"(d[2]), "+f"(d[3])
        : "r"(a[0]), "r"(a[1]), "r"(a[2]), "r"(a[3]), "r"(b[0]), "r"(b[1]));
}
__device__ __forceinline__ void split3(float v, uint16_t& s0, uint16_t& s1, uint16_t& s2) {
    __nv_bfloat16 b0 = __float2bfloat16(v);
    float r = v - __bfloat162float(b0);
    __nv_bfloat16 b1 = __float2bfloat16(r);
    float r2 = r - __bfloat162float(b1);
    __nv_bfloat16 b2 = __float2bfloat16(r2);
    s0 = __bfloat16_as_ushort(b0);
    s1 = __bfloat16_as_ushort(b1);
    s2 = __bfloat16_as_ushort(b2);
}
__device__ __forceinline__ uint32_t pack2u(uint16_t lo, uint16_t hi) {
    return (uint32_t)lo | ((uint32_t)hi << 16);
}

__global__ void compute_D_kernel() {
    int k = blockIdx.x;
    int h = threadIdx.x;
    float a = 3.14159274101257324f * ((float)h + 0.5f);
    a = a * (float)k;
    a = a * 0.00390625f;
    float v = (float)cos((double)a);
    v = v * 0.088388347f;
    if (k == 0) v = v * 0.70710677f;
    uint16_t s0, s1, s2;
    split3(v, s0, s1, s2);
    int i = k * NN + h;
    g_D0[i] = __ushort_as_bfloat16(s0);
    g_D1[i] = __ushort_as_bfloat16(s1);
    g_D2[i] = __ushort_as_bfloat16(s2);
}

__device__ __forceinline__ float log_precise(float x) {
    unsigned ix = __float_as_uint(x);
    int e = (int)(ix >> 23) - 126;
    float m = __uint_as_float((ix & 0x007FFFFFu) | 0x3F000000u);
    if (m < 0.70710678f) { m = m + m; e -= 1; }
    float f = m - 1.0f;
    float z = f * f;
    float p =            7.0376836292e-2f;
    p = fmaf(p, f, -1.1514610310e-1f);
    p = fmaf(p, f,  1.1676998740e-1f);
    p = fmaf(p, f, -1.2420140846e-1f);
    p = fmaf(p, f,  1.4249322787e-1f);
    p = fmaf(p, f, -1.6668057665e-1f);
    p = fmaf(p, f,  2.0000714765e-1f);
    p = fmaf(p, f, -2.4999993993e-1f);
    p = fmaf(p, f,  3.3333331174e-1f);
    float y = f * z * p;
    float fe = (float)e;
    y = fmaf(fe, -2.12194440e-4f, y);
    y = fmaf(-0.5f, z, y);
    float r = f + y;
    r = fmaf(fe, 0.693359375f, r);
    return r;
}

// D splits tile -> smem, nrows rows from row0, 16 k-cols from col0
__device__ __forceinline__ void load_D_tile(uint8_t* sm, int row0, int col0,
                                            int tid, int nrows) {
    int row = tid >> 1, half = tid & 1;
    if (row < nrows) {
        size_t g = (size_t)(row0 + row) * NN + col0 + half * 8;
        uint8_t* dst = sm + row * ROWB + half * 16;
        *(uint4*)(dst +  0) = *(const uint4*)(g_D0 + g);
        *(uint4*)(dst + 32) = *(const uint4*)(g_D1 + g);
        *(uint4*)(dst + 64) = *(const uint4*)(g_D2 + g);
    }
}

// warp-tile MMA body: one (Aseg,Bseg) product block into given accumulator
__device__ __forceinline__ void mma_block(float acc[2][4][4], uint32_t aBase,
                                          uint32_t bBase, int segA, int segB) {
    uint32_t af[2][4];
    #pragma unroll
    for (int mt = 0; mt < 2; mt++)
        ldsm_x4(af[mt], aBase + mt * 16 * ROWB + segA * 32);
    uint32_t bfr[2][4];
    #pragma unroll
    for (int h2 = 0; h2 < 2; h2++)
        ldsm_x4(bfr[h2], bBase + h2 * 16 * ROWB + segB * 32);
    #pragma unroll
    for (int mt = 0; mt < 2; mt++)
        #pragma unroll
        for (int nt = 0; nt < 4; nt++)
            mma_bf16(acc[mt][nt], af[mt], &bfr[nt >> 1][(nt & 1) * 2]);
}

// 6 split-products, big product (0,0) into accB, rest into accS
__device__ __forceinline__ void mma_chunk(const uint8_t* sA, const uint8_t* sB,
                                          float accB[2][4][4], float accS[2][4][4],
                                          int lane, int warp_m, int warp_n) {
    uint32_t aBase = smem_u32(sA) + (warp_m * 32 + (lane & 15)) * ROWB + (lane >> 4) * 16;
    uint32_t bBase = smem_u32(sB) +
        (warp_n * 32 + ((lane >> 4) & 1) * 8 + (lane & 7)) * ROWB + ((lane >> 3) & 1) * 16;
    mma_block(accB, aBase, bBase, 0, 0);
    mma_block(accS, aBase, bBase, 0, 1);
    mma_block(accS, aBase, bBase, 0, 2);
    mma_block(accS, aBase, bBase, 1, 0);
    mma_block(accS, aBase, bBase, 1, 1);
    mma_block(accS, aBase, bBase, 2, 0);
}

#define ZERO_ACC(A)                                        \
    _Pragma("unroll") for (int i = 0; i < 2; i++)          \
    _Pragma("unroll") for (int j = 0; j < 4; j++)          \
    _Pragma("unroll") for (int e = 0; e < 4; e++) A[i][j][e] = 0.0f;

// ---------------------------------------------------------------------------
// GEMM1: T[k,w] = sum_h D[k,h] * x[b,h,w,c];  CTA tile 128(k) x 64(w)
// ---------------------------------------------------------------------------
__global__ void __launch_bounds__(256, 2) dct_gemm1(const float* __restrict__ x) {
    __shared__ __align__(16) uint8_t sA[TILEA];
    __shared__ __align__(16) uint8_t sB[TILEB_SZ];
    int tid = threadIdx.x, wid = tid >> 5, lane = tid & 31;
    int warp_m = wid & 3, warp_n = wid >> 2;
    int p = blockIdx.y, b = p / 3, c = p - 3 * b;
    int tk = (blockIdx.x >> 2) * 128, tw = (blockIdx.x & 3) * 64;
    const float* xb = x + (size_t)b * NN * NN * NC + c;

    float accB[2][4][4], accS[2][4][4];
    ZERO_ACC(accB); ZERO_ACC(accS);

    for (int t = 0; t < 16; t++) {
        int h0 = t * 16;
        load_D_tile(sA, tk, h0, tid, 128);      // A[m][k] = D[tk+m][h0+k]
        #pragma unroll
        for (int l = 0; l < 2; l++) {           // B[n][k] = x[h0+k][tw+n][c]
            int idx = tid + l * 256;
            int n = idx & 63, kp = idx >> 6;    // kp 0..7
            const float* px = xb + (size_t)(h0 + 2 * kp) * (NN * NC) + (size_t)(tw + n) * NC;
            float v0 = px[0], v1 = px[NN * NC];
            uint16_t a0, a1, a2, b0, b1, b2;
            split3(v0, a0, a1, a2);
            split3(v1, b0, b1, b2);
            uint8_t* dst = sB + n * ROWB + kp * 4;
            *(uint32_t*)(dst +  0) = pack2u(a0, b0);
            *(uint32_t*)(dst + 32) = pack2u(a1, b1);
            *(uint32_t*)(dst + 64) = pack2u(a2, b2);
        }
        __syncthreads();
        mma_chunk(sA, sB, accB, accS, lane, warp_m, warp_n);
        __syncthreads();
    }

    float* S = g_S1 + (size_t)p * NN * NN;
    int r = lane >> 2, q = (lane & 3) * 2;
    #pragma unroll
    for (int mt = 0; mt < 2; mt++) {
        int m0 = tk + warp_m * 32 + mt * 16 + r;
        #pragma unroll
        for (int nt = 0; nt < 4; nt++) {
            int ncol = tw + warp_n * 32 + nt * 8 + q;
            float2 v01 = make_float2(accB[mt][nt][0] + accS[mt][nt][0],
                                     accB[mt][nt][1] + accS[mt][nt][1]);
            float2 v23 = make_float2(accB[mt][nt][2] + accS[mt][nt][2],
                                     accB[mt][nt][3] + accS[mt][nt][3]);
            *(float2*)(S + (size_t)m0 * NN + ncol) = v01;
            *(float2*)(S + (size_t)(m0 + 8) * NN + ncol) = v23;
        }
    }
}

// ---------------------------------------------------------------------------
// GEMM2: U[k,j] = sum_w T[k,w] * D[j,w]; fused log/normalize epilogue.
// CTA tile 128(k) x 64(j)
// ---------------------------------------------------------------------------
__global__ void __launch_bounds__(256, 2) dct_gemm2(const float* __restrict__ mean,
                                                    const float* __restrict__ stdv,
                                                    float* __restrict__ out) {
    __shared__ __align__(16) uint8_t sA[TILEA];
    __shared__ __align__(16) uint8_t sB[TILEB_SZ];
    int tid = threadIdx.x, wid = tid >> 5, lane = tid & 31;
    int warp_m = wid & 3, warp_n = wid >> 2;
    int p = blockIdx.y, b = p / 3, c = p - 3 * b;
    int tk = (blockIdx.x >> 2) * 128, tj = (blockIdx.x & 3) * 64;
    const float* T = g_S1 + (size_t)p * NN * NN;

    float accB[2][4][4], accS[2][4][4];
    ZERO_ACC(accB); ZERO_ACC(accS);

    for (int t = 0; t < 16; t++) {
        int w0 = t * 16;
        #pragma unroll
        for (int l = 0; l < 4; l++) {           // A[m][k] = T[tk+m][w0+k], split
            int idx = tid + l * 256;
            int row = idx >> 3, kp = idx & 7;
            float2 v = *(const float2*)(T + (size_t)(tk + row) * NN + w0 + kp * 2);
            uint16_t a0, a1, a2, b0, b1, b2;
            split3(v.x, a0, a1, a2);
            split3(v.y, b0, b1, b2);
            uint8_t* dst = sA + row * ROWB + kp * 4;
            *(uint32_t*)(dst +  0) = pack2u(a0, b0);
            *(uint32_t*)(dst + 32) = pack2u(a1, b1);
            *(uint32_t*)(dst + 64) = pack2u(a2, b2);
        }
        load_D_tile(sB, tj, w0, tid, 64);       // B[n][k] = D[tj+n][w0+k]
        __syncthreads();
        mma_chunk(sA, sB, accB, accS, lane, warp_m, warp_n);
        __syncthreads();
    }

    int r = lane >> 2, q = (lane & 3) * 2;
    #pragma unroll
    for (int mt = 0; mt < 2; mt++) {
        #pragma unroll
        for (int nt = 0; nt < 4; nt++) {
            #pragma unroll
            for (int e = 0; e < 4; e++) {
                int krow = tk + warp_m * 32 + mt * 16 + r + (e >> 1) * 8;
                int j = tj + warp_n * 32 + nt * 8 + q + (e & 1);
                float y = accB[mt][nt][e] + accS[mt][nt][e];
                float z = log_precise(fabsf(y) + 1e-13f);
                int mi = (krow * NN + j) * NC + c;
                out[((size_t)(b * NN + krow) * NN + j) * NC + c] =
                    (z - mean[mi]) / stdv[mi];
            }
        }
    }
}

// ---------------------------------------------------------------------------
extern "C" void kernel_launch(void* const* d_in, const int* in_sizes, int n_in,
                              void* d_out, int out_size) {
    const float* x    = (const float*)d_in[0];
    const float* mean = (const float*)d_in[1];
    const float* stdv = (const float*)d_in[2];
    float* out = (float*)d_out;

    compute_D_kernel<<<256, 256>>>();
    dct_gemm1<<<dim3(8, NPLANES), 256>>>(x);
    dct_gemm2<<<dim3(8, NPLANES), 256>>>(mean, stdv, out);
}